// round 13
// baseline (speedup 1.0000x reference)
#include <cuda_runtime.h>
#include <math.h>

#define HH 512
#define WW 512
#define BB 32
#define CCH 3
#define NK 6
#define NCHUNK 8
#define CROWS 64          // HH / NCHUNK
#define R3ROWS 8
#define TWO_PI 6.283185307179586f

typedef unsigned long long u64;

__device__ __forceinline__ u64 pk(float lo, float hi) {
    u64 r; asm("mov.b64 %0,{%1,%2};" : "=l"(r) : "f"(lo), "f"(hi)); return r;
}
__device__ __forceinline__ float2 upk(u64 v) {
    float2 f; asm("mov.b64 {%0,%1},%2;" : "=f"(f.x), "=f"(f.y) : "l"(v)); return f;
}
__device__ __forceinline__ u64 fma2_(u64 a, u64 b, u64 c) {
    u64 d; asm("fma.rn.f32x2 %0,%1,%2,%3;" : "=l"(d) : "l"(a), "l"(b), "l"(c)); return d;
}
__device__ __forceinline__ u64 add2_(u64 a, u64 b) {
    u64 d; asm("add.rn.f32x2 %0,%1,%2;" : "=l"(d) : "l"(a), "l"(b)); return d;
}

// Scratch (device globals — no allocation allowed)
// g_cols: per (bc,chunk), 7 coefficient planes of 512 w's:
//   c=0: S0 ; c=1,2: C1 re,im ; c=3,4: C2 re,im ; c=5,6: C3 re,im
__device__ float  g_cols[BB * CCH * NCHUNK * 7 * WW];
__device__ float4 g_d4[BB * CCH * HH * 3];   // [bc][h][12 floats]: |z|^2 autocorr coeffs

// ---------------------------------------------------------------------------
// Kernel 1: column sums only (NO projection, NO reduction — moved to k2).
// Real-input symmetry: 7 accumulators, 3 complex twiddles per row.
// Thread = float4 of w. Block 128, grid (8, 96) = 768 blocks.
// ---------------------------------------------------------------------------
__global__ __launch_bounds__(128) void k1_coldft(const float* __restrict__ x) {
    const int chunk = blockIdx.x;
    const int bc    = blockIdx.y;
    const int t     = threadIdx.x;
    const int h0    = chunk * CROWS;

    __shared__ __align__(16) u64 twc[CROWS][3], tws[CROWS][3];

    for (int i = t; i < CROWS * 3; i += 128) {
        int hl = i / 3, K = (i % 3) + 1;
        float a = TWO_PI * (float)(h0 + hl) * (1.0f / (float)HH) * (float)K;
        float s, c; __sincosf(a, &s, &c);
        twc[hl][K - 1] = pk(c, c);
        tws[hl][K - 1] = pk(s, s);
    }
    __syncthreads();

    u64 S0[2] = {0ULL, 0ULL};
    u64 Cr[3][2], Ci[3][2];
#pragma unroll
    for (int K = 0; K < 3; K++) { Cr[K][0] = Cr[K][1] = 0ULL; Ci[K][0] = Ci[K][1] = 0ULL; }

    const float4* xp = (const float4*)(x + (size_t)bc * HH * WW + (size_t)h0 * WW) + t;
#pragma unroll 8
    for (int hl = 0; hl < CROWS; ++hl) {
        float4 v = __ldg(xp + (size_t)hl * (WW / 4));
        u64 v01 = pk(v.x, v.y), v23 = pk(v.z, v.w);
        S0[0] = add2_(S0[0], v01);
        S0[1] = add2_(S0[1], v23);
#pragma unroll
        for (int K = 0; K < 3; K++) {
            u64 cc = twc[hl][K], ss = tws[hl][K];
            Cr[K][0] = fma2_(v01, cc, Cr[K][0]);
            Ci[K][0] = fma2_(v01, ss, Ci[K][0]);
            Cr[K][1] = fma2_(v23, cc, Cr[K][1]);
            Ci[K][1] = fma2_(v23, ss, Ci[K][1]);
        }
    }

    // store 7 coefficient planes as float4 (w = 4t..4t+3)
    float4* gp = (float4*)(g_cols + ((size_t)(bc * NCHUNK + chunk) * 7) * WW) + t;
    {
        float2 a0 = upk(S0[0]), a1 = upk(S0[1]);
        gp[0] = make_float4(a0.x, a0.y, a1.x, a1.y);
    }
#pragma unroll
    for (int K = 0; K < 3; K++) {
        float2 r0 = upk(Cr[K][0]), r1 = upk(Cr[K][1]);
        float2 i0 = upk(Ci[K][0]), i1 = upk(Ci[K][1]);
        gp[(1 + 2 * K) * (WW / 4)] = make_float4(r0.x, r0.y, r1.x, r1.y);
        gp[(2 + 2 * K) * (WW / 4)] = make_float4(i0.x, i0.y, i1.x, i1.y);
    }
}

// ---------------------------------------------------------------------------
// Kernel 2: per (b,c):
//  phase A (t=w): sum chunk partials, project onto E_k(w), block-reduce -> F[6][6]
//  phase B (t=h): gg[h][k] = sum_u F[u][k] D_u(h); autocorr coeffs -> g_d4.
// grid 96, block 512.
// ---------------------------------------------------------------------------
__global__ __launch_bounds__(512) void k2_reduce() {
    const int bc = blockIdx.x;
    const int t  = threadIdx.x;
    const int wid = t >> 5, lid = t & 31;

    __shared__ float part[16][72];
    __shared__ float F[72];

    // ---- phase A ----
    {
        // sum the 8 chunk partials for this w
        float S0 = 0.f, C[3][2] = {{0,0},{0,0},{0,0}};
        const float* gp = g_cols + ((size_t)bc * NCHUNK * 7) * WW + t;
#pragma unroll
        for (int c = 0; c < NCHUNK; c++) {
            const float* base = gp + (size_t)c * 7 * WW;
            S0 += base[0];
#pragma unroll
            for (int K = 0; K < 3; K++) {
                C[K][0] += base[(1 + 2 * K) * WW];
                C[K][1] += base[(2 + 2 * K) * WW];
            }
        }
        // reconstruct col_u (u = 3: (S0,0); u = 3∓K: (CKr, ±CKi))
        float gr_[6], gi_[6];
        gr_[3] = S0; gi_[3] = 0.f;
#pragma unroll
        for (int K = 1; K <= 3; K++) {
            gr_[3 - K] = C[K - 1][0]; gi_[3 - K] = C[K - 1][1];
            if (3 + K < 6) { gr_[3 + K] = C[K - 1][0]; gi_[3 + K] = -C[K - 1][1]; }
        }

        // E_k(w) = e^{-i (k-3) phi_w}
        float Ec[6], Es[6];
        {
            float phi = TWO_PI * (float)t * (1.0f / (float)WW);
            float c1, s1; __sincosf(phi, &s1, &c1);
            float c2 = c1 * c1 - s1 * s1, s2 = 2.f * c1 * s1;
            float c3 = c2 * c1 - s2 * s1, s3 = c2 * s1 + s2 * c1;
            Ec[0] = c3; Es[0] = s3;
            Ec[1] = c2; Es[1] = s2;
            Ec[2] = c1; Es[2] = s1;
            Ec[3] = 1.f; Es[3] = 0.f;
            Ec[4] = c1; Es[4] = -s1;
            Ec[5] = c2; Es[5] = -s2;
        }

        // per-u projection + warp reduce (keeps register pressure low)
#pragma unroll
        for (int u = 0; u < 6; u++) {
            float pr[6], pi[6];
            float gr = gr_[u], gi = gi_[u];
#pragma unroll
            for (int k = 0; k < 6; k++) {
                pr[k] = gr * Ec[k] - gi * Es[k];
                pi[k] = gr * Es[k] + gi * Ec[k];
            }
#pragma unroll
            for (int off = 16; off >= 1; off >>= 1) {
#pragma unroll
                for (int k = 0; k < 6; k++) {
                    pr[k] += __shfl_xor_sync(0xFFFFFFFFu, pr[k], off);
                    pi[k] += __shfl_xor_sync(0xFFFFFFFFu, pi[k], off);
                }
            }
            if (lid == 0) {
#pragma unroll
                for (int k = 0; k < 6; k++) {
                    part[wid][(u * 6 + k) * 2 + 0] = pr[k];
                    part[wid][(u * 6 + k) * 2 + 1] = pi[k];
                }
            }
        }
    }
    __syncthreads();
    if (t < 72) {
        float s = 0.f;
#pragma unroll
        for (int q = 0; q < 16; q++) s += part[q][t];
        F[t] = s * (1.0f / ((float)HH * (float)WW));
    }
    __syncthreads();

    // ---- phase B: t = h ----
    {
        float psi = TWO_PI * (float)t * (1.0f / (float)HH);
        float d1c, d1s; __sincosf(psi, &d1s, &d1c);
        float d2c = d1c * d1c - d1s * d1s, d2s = 2.f * d1c * d1s;
        float d3c = d2c * d1c - d2s * d1s, d3s = d2c * d1s + d2s * d1c;
        float Dc[6] = { d3c,  d2c,  d1c,  1.f, d1c, d2c };
        float Ds[6] = { -d3s, -d2s, -d1s, 0.f, d1s, d2s };

        float gr[6], gi[6];
#pragma unroll
        for (int k = 0; k < 6; k++) {
            float r = 0.f, im = 0.f;
#pragma unroll
            for (int u = 0; u < 6; u++) {
                float Fr = F[(u * 6 + k) * 2 + 0];
                float Fi = F[(u * 6 + k) * 2 + 1];
                r  += Fr * Dc[u] - Fi * Ds[u];
                im += Fr * Ds[u] + Fi * Dc[u];
            }
            gr[k] = r; gi[k] = im;
        }

        // autocorrelation coefficients:
        // |z|^2 = c0 + sum_m 2Re(c_m)cos(m phi) - 2Im(c_m)sin(m phi)
        float d[12];
        {
            float c0 = 0.f;
#pragma unroll
            for (int k = 0; k < 6; k++) c0 = fmaf(gr[k], gr[k], fmaf(gi[k], gi[k], c0));
            d[0] = c0;
#pragma unroll
            for (int m = 1; m <= 5; m++) {
                float re = 0.f, im = 0.f;
#pragma unroll
                for (int k = m; k < 6; k++) {
                    re = fmaf(gr[k], gr[k - m], fmaf(gi[k], gi[k - m], re));
                    im = fmaf(gi[k], gr[k - m], fmaf(-gr[k], gi[k - m], im));
                }
                d[2 * m - 1] = 2.f * re;
                d[2 * m]     = -2.f * im;
            }
            d[11] = 0.f;
        }

        float4* dp = g_d4 + ((size_t)bc * HH + t) * 3;
        dp[0] = make_float4(d[0], d[1], d[2],  d[3]);
        dp[1] = make_float4(d[4], d[5], d[6],  d[7]);
        dp[2] = make_float4(d[8], d[9], d[10], d[11]);
    }
}

// ---------------------------------------------------------------------------
// Kernel 3 (identical to R12, measured ~62us): |z| via autocorr, MLP,
// residual, clip. Thread = 2 adjacent pixels. grid (H/8, B), block 256.
// ---------------------------------------------------------------------------
__global__ __launch_bounds__(256) void k3_final(const float* __restrict__ w1,
                                                const float* __restrict__ b1,
                                                const float* __restrict__ w2,
                                                const float* __restrict__ b2,
                                                float* __restrict__ out) {
    const int b  = blockIdx.y;
    const int h0 = blockIdx.x * R3ROWS;
    const int t  = threadIdx.x;   // pixel pair (2t, 2t+1)

    __shared__ __align__(16) float sd[R3ROWS * 3 * 12];  // [r][ch][12]
    __shared__ float wt[64];

    if (t < 72) {   // 72 float4 = 288 floats
        int r  = t / 9;
        int ch = (t % 9) / 3;
        int q  = t % 3;
        ((float4*)sd)[t] = g_d4[(((size_t)(b * 3 + ch) * HH) + (h0 + r)) * 3 + q];
    } else if (t >= 128 && t < 128 + 24) {
        wt[t - 128] = w1[t - 128];
    } else if (t >= 128 + 24 && t < 128 + 32) {
        wt[t - 128] = b1[t - 152];
    } else if (t >= 128 + 32 && t < 128 + 56) {
        wt[t - 128] = w2[t - 160];
    } else if (t >= 128 + 56 && t < 128 + 59) {
        wt[t - 128] = b2[t - 184];
    }
    __syncthreads();

    float W1r[8][3], B1r[8], W2r[3][8], B2r[3];
#pragma unroll
    for (int j = 0; j < 8; j++) {
#pragma unroll
        for (int cc = 0; cc < 3; cc++) W1r[j][cc] = wt[j * 3 + cc];
        B1r[j] = wt[24 + j];
    }
#pragma unroll
    for (int cc = 0; cc < 3; cc++) {
#pragma unroll
        for (int j = 0; j < 8; j++) W2r[cc][j] = wt[32 + cc * 8 + j];
        B2r[cc] = wt[56 + cc];
    }

    // cos/sin basis for m=1..5, both pixels (Chebyshev recurrence, hoisted)
    float cA[6], sA[6], cB[6], sB[6];
    {
        const int w0 = 2 * t;
        __sincosf(TWO_PI * (float)w0       * (1.0f / (float)WW), &sA[1], &cA[1]);
        __sincosf(TWO_PI * (float)(w0 + 1) * (1.0f / (float)WW), &sB[1], &cB[1]);
        float kA = 2.f * cA[1], kB = 2.f * cB[1];
        cA[0] = 1.f; sA[0] = 0.f; cB[0] = 1.f; sB[0] = 0.f;
#pragma unroll
        for (int m = 2; m <= 5; m++) {
            cA[m] = fmaf(kA, cA[m - 1], -cA[m - 2]);
            sA[m] = fmaf(kA, sA[m - 1], -sA[m - 2]);
            cB[m] = fmaf(kB, cB[m - 1], -cB[m - 2]);
            sB[m] = fmaf(kB, sB[m - 1], -sB[m - 2]);
        }
    }

#pragma unroll
    for (int r = 0; r < R3ROWS; ++r) {
        float lpA[3], lpB[3];
#pragma unroll
        for (int ch = 0; ch < 3; ch++) {
            const float* dd = &sd[(r * 3 + ch) * 12];
            float sa = dd[0], sb = dd[0];
#pragma unroll
            for (int m = 1; m <= 5; m++) {
                float dre = dd[2 * m - 1], dim = dd[2 * m];
                sa = fmaf(dre, cA[m], fmaf(dim, sA[m], sa));
                sb = fmaf(dre, cB[m], fmaf(dim, sB[m], sb));
            }
            sa = fmaxf(sa, 0.f);
            sb = fmaxf(sb, 0.f);
            lpA[ch] = sa * __frsqrt_rn(fmaxf(sa, 1e-30f));
            lpB[ch] = sb * __frsqrt_rn(fmaxf(sb, 1e-30f));
        }

        float hA[8], hB[8];
#pragma unroll
        for (int j = 0; j < 8; j++) {
            float aA = B1r[j], aB = B1r[j];
            aA = fmaf(W1r[j][0], lpA[0], aA);  aB = fmaf(W1r[j][0], lpB[0], aB);
            aA = fmaf(W1r[j][1], lpA[1], aA);  aB = fmaf(W1r[j][1], lpB[1], aB);
            aA = fmaf(W1r[j][2], lpA[2], aA);  aB = fmaf(W1r[j][2], lpB[2], aB);
            hA[j] = fmaxf(aA, 0.f);            hB[j] = fmaxf(aB, 0.f);
        }

#pragma unroll
        for (int ch = 0; ch < 3; ch++) {
            float yA = B2r[ch] + lpA[ch];
            float yB = B2r[ch] + lpB[ch];
#pragma unroll
            for (int j = 0; j < 8; j++) {
                yA = fmaf(W2r[ch][j], hA[j], yA);
                yB = fmaf(W2r[ch][j], hB[j], yB);
            }
            float2 yv;
            yv.x = __saturatef(yA);
            yv.y = __saturatef(yB);
            float2* orow = (float2*)(out + (((size_t)(b * 3 + ch) * HH) + (h0 + r)) * WW);
            orow[t] = yv;
        }
    }
}

// ---------------------------------------------------------------------------
extern "C" void kernel_launch(void* const* d_in, const int* in_sizes, int n_in,
                              void* d_out, int out_size) {
    const float* x  = (const float*)d_in[0];
    const float* w1 = (const float*)d_in[1];
    const float* b1 = (const float*)d_in[2];
    const float* w2 = (const float*)d_in[3];
    const float* b2 = (const float*)d_in[4];
    float* out = (float*)d_out;

    k1_coldft<<<dim3(NCHUNK, BB * CCH), 128>>>(x);
    k2_reduce<<<BB * CCH, 512>>>();
    k3_final<<<dim3(HH / R3ROWS, BB), 256>>>(w1, b1, w2, b2, out);
}